// round 2
// baseline (speedup 1.0000x reference)
#include <cuda_runtime.h>
#include <math.h>

// Shapes are fixed by the problem: B=512, L=256, L1=256, D=128.
#define B_   512
#define L_   256
#define D_   128
#define L1_  256
#define RS   129          // padded smem row stride (conflict-free: 129 % 32 == 1)
#define EPSF 0.01f

// Scratch for h_last [B, D] (no allocations allowed -> device global)
__device__ float g_hlast[B_ * D_];

// ---------------------------------------------------------------------------
// Kernel A: per-batch self cosine-attention, restricted to rows where
// last*mask != 0, accumulating h_last[b] = sum_i (h_self_i + h_i).
// One CTA per batch, 256 threads, hist_1[b] resident in SMEM.
// ---------------------------------------------------------------------------
__global__ __launch_bounds__(256, 1)
void self_attn_kernel(const int* __restrict__ seq,
                      const int* __restrict__ last,
                      const float* __restrict__ h1)
{
    extern __shared__ float sm[];
    float* Hs   = sm;                      // [256][129]
    float* inv  = Hs + L_ * RS;            // [256] rsqrt(||h_i||^2 + eps)
    float* msk  = inv + L_;                // [256] key mask
    float* wrow = msk + L_;                // [8 warps][4 rows][256] w values
    float* hlp  = wrow + 8 * 4 * L_;       // [8 warps][128] per-warp h_last partials
    int*   sel  = (int*)(hlp + 8 * D_);    // [256] selected row indices
    __shared__ int nsel_s;

    const int b    = blockIdx.x;
    const int tid  = threadIdx.x;
    const int wid  = tid >> 5;
    const int lane = tid & 31;

    // ---- load hist_1[b] into padded SMEM (float4 gmem reads) ----
    const float* src = h1 + (size_t)b * L_ * D_;
    for (int idx = tid; idx < L_ * D_ / 4; idx += 256) {
        float4 v = ((const float4*)src)[idx];
        int i = idx >> 5;            // idx / (D/4)
        int d = (idx & 31) << 2;
        float* p = Hs + i * RS + d;
        p[0] = v.x; p[1] = v.y; p[2] = v.z; p[3] = v.w;
    }
    for (int idx = tid; idx < 8 * D_; idx += 256) hlp[idx] = 0.f;
    __syncthreads();

    // ---- norms, mask, selection ----
    if (tid < L_) {
        const float* r = Hs + tid * RS;
        float s = 0.f;
        #pragma unroll 8
        for (int d = 0; d < D_; ++d) s += r[d] * r[d];
        inv[tid] = rsqrtf(s + EPSF);
        msk[tid] = (seq[b * L_ + tid] != 0) ? 1.f : 0.f;
    }
    if (tid == 0) {   // deterministic, ordered selection list
        int n = 0;
        for (int i = 0; i < L_; ++i)
            if (last[b * L_ + i] != 0 && seq[b * L_ + i] != 0) sel[n++] = i;
        nsel_s = n;
    }
    __syncthreads();
    const int nsel = nsel_s;

    float* myw  = wrow + wid * 4 * L_;
    float* myhl = hlp + wid * D_;

    // ---- main loop: 4 query rows per warp per iteration ----
    for (int base = wid * 4; base < nsel; base += 32) {
        const int nr = nsel - base;   // >= 1
        const int i0 = sel[base];
        const int i1 = sel[base + ((nr > 1) ? 1 : 0)];
        const int i2 = sel[base + ((nr > 2) ? 2 : 0)];
        const int i3 = sel[base + ((nr > 3) ? 3 : 0)];

        // --- S phase: dots for 4 rows x 8 key-columns per lane ---
        float acc[4][8];
        #pragma unroll
        for (int r = 0; r < 4; ++r)
            #pragma unroll
            for (int c = 0; c < 8; ++c) acc[r][c] = 0.f;

        const float* R0 = Hs + i0 * RS;
        const float* R1 = Hs + i1 * RS;
        const float* R2 = Hs + i2 * RS;
        const float* R3 = Hs + i3 * RS;
        const float* Kp = Hs + lane * RS;

        #pragma unroll 4
        for (int d = 0; d < D_; ++d) {
            const float q0 = R0[d], q1 = R1[d], q2 = R2[d], q3 = R3[d];
            #pragma unroll
            for (int c = 0; c < 8; ++c) {
                const float kv = Kp[c * 32 * RS + d];
                acc[0][c] += q0 * kv;
                acc[1][c] += q1 * kv;
                acc[2][c] += q2 * kv;
                acc[3][c] += q3 * kv;
            }
        }

        // --- w = exp(cos)*mask, row sums ---
        const float iq0 = inv[i0], iq1 = inv[i1], iq2 = inv[i2], iq3 = inv[i3];
        float ws0 = 0.f, ws1 = 0.f, ws2 = 0.f, ws3 = 0.f;
        #pragma unroll
        for (int c = 0; c < 8; ++c) {
            const int j = lane + 32 * c;
            const float ivj = inv[j];
            const float mj  = msk[j];
            float w;
            w = __expf(acc[0][c] * iq0 * ivj) * mj; ws0 += w; myw[0 * L_ + j] = w;
            w = __expf(acc[1][c] * iq1 * ivj) * mj; ws1 += w; myw[1 * L_ + j] = w;
            w = __expf(acc[2][c] * iq2 * ivj) * mj; ws2 += w; myw[2 * L_ + j] = w;
            w = __expf(acc[3][c] * iq3 * ivj) * mj; ws3 += w; myw[3 * L_ + j] = w;
        }
        #pragma unroll
        for (int off = 16; off; off >>= 1) {
            ws0 += __shfl_xor_sync(0xffffffffu, ws0, off);
            ws1 += __shfl_xor_sync(0xffffffffu, ws1, off);
            ws2 += __shfl_xor_sync(0xffffffffu, ws2, off);
            ws3 += __shfl_xor_sync(0xffffffffu, ws3, off);
        }
        __syncwarp();   // myw writes visible before cross-lane reads

        // --- O phase: acc_d = sum_j w_j * H[j][d]; lane covers 4 d's ---
        float oacc[4][4];
        #pragma unroll
        for (int r = 0; r < 4; ++r)
            #pragma unroll
            for (int c = 0; c < 4; ++c) oacc[r][c] = 0.f;

        for (int j = 0; j < L_; ++j) {
            const float w0 = myw[0 * L_ + j];
            const float w1 = myw[1 * L_ + j];
            const float w2 = myw[2 * L_ + j];
            const float w3 = myw[3 * L_ + j];
            const float* Hj = Hs + j * RS + lane;
            #pragma unroll
            for (int c = 0; c < 4; ++c) {
                const float hv = Hj[c * 32];
                oacc[0][c] += w0 * hv;
                oacc[1][c] += w1 * hv;
                oacc[2][c] += w2 * hv;
                oacc[3][c] += w3 * hv;
            }
        }

        // --- accumulate (h_self + h) into this warp's h_last partial ---
        const int   ii[4] = { i0, i1, i2, i3 };
        const float ws[4] = { ws0, ws1, ws2, ws3 };
        #pragma unroll
        for (int r = 0; r < 4; ++r) {
            if (base + r < nsel) {
                const float invw = 1.f / ws[r];
                const float* Hi = Hs + ii[r] * RS + lane;
                #pragma unroll
                for (int c = 0; c < 4; ++c) {
                    const int d = lane + 32 * c;
                    myhl[d] += oacc[r][c] * invw + Hi[c * 32];
                }
            }
        }
        __syncwarp();   // protect myw against next iteration's writes
    }

    __syncthreads();
    if (tid < D_) {   // deterministic fixed-order reduction over warps
        float s = 0.f;
        #pragma unroll
        for (int w = 0; w < 8; ++w) s += hlp[w * D_ + tid];
        g_hlast[b * D_ + tid] = s;
    }
}

// ---------------------------------------------------------------------------
// Kernel B: cross cosine-attention of h_last over hist_2, then relu(h @ W).
// One CTA per batch, 256 threads. Memory-bound, tiny.
// ---------------------------------------------------------------------------
__global__ __launch_bounds__(256, 4)
void cross_kernel(const int* __restrict__ seq1,
                  const float* __restrict__ h2,
                  const float* __restrict__ W,
                  float* __restrict__ out)
{
    __shared__ float hl[D_];
    __shared__ float w2s[L1_];
    __shared__ float wsump[8];
    __shared__ float haccp[8][D_];
    __shared__ float hv[D_];
    __shared__ float invq_s;

    const int b    = blockIdx.x;
    const int tid  = threadIdx.x;
    const int wid  = tid >> 5;
    const int lane = tid & 31;

    if (tid < D_) hl[tid] = g_hlast[b * D_ + tid];
    __syncthreads();

    if (tid < 32) {   // ||h_last||^2 via one warp
        float s = 0.f;
        #pragma unroll
        for (int c = 0; c < 4; ++c) { float v = hl[tid + 32 * c]; s += v * v; }
        #pragma unroll
        for (int off = 16; off; off >>= 1) s += __shfl_xor_sync(0xffffffffu, s, off);
        if (tid == 0) invq_s = rsqrtf(s + EPSF);
    }
    __syncthreads();
    const float invq = invq_s;
    const float* H2 = h2 + (size_t)b * L1_ * D_;

    // pass 1: w2[k] and per-warp wsum (fixed order -> deterministic)
    float wpart = 0.f;
    for (int k = wid; k < L1_; k += 8) {
        float4 v = ((const float4*)(H2 + k * D_))[lane];
        float dot = v.x * hl[lane * 4]     + v.y * hl[lane * 4 + 1]
                  + v.z * hl[lane * 4 + 2] + v.w * hl[lane * 4 + 3];
        float nk  = v.x * v.x + v.y * v.y + v.z * v.z + v.w * v.w;
        #pragma unroll
        for (int off = 16; off; off >>= 1) {
            dot += __shfl_xor_sync(0xffffffffu, dot, off);
            nk  += __shfl_xor_sync(0xffffffffu, nk,  off);
        }
        float w = __expf(dot * rsqrtf(nk + EPSF) * invq)
                * ((seq1[b * L1_ + k] != 0) ? 1.f : 0.f);
        if (lane == 0) w2s[k] = w;
        wpart += w;   // identical on all lanes after full reduction
    }
    if (lane == 0) wsump[wid] = wpart;
    __syncthreads();

    // pass 2: weighted sum of hist_2 rows (per-warp partials)
    float a0 = 0.f, a1 = 0.f, a2 = 0.f, a3 = 0.f;
    for (int k = wid; k < L1_; k += 8) {
        const float w = w2s[k];
        float4 v = ((const float4*)(H2 + k * D_))[lane];
        a0 += w * v.x; a1 += w * v.y; a2 += w * v.z; a3 += w * v.w;
    }
    haccp[wid][lane * 4]     = a0;
    haccp[wid][lane * 4 + 1] = a1;
    haccp[wid][lane * 4 + 2] = a2;
    haccp[wid][lane * 4 + 3] = a3;
    __syncthreads();

    if (tid < D_) {
        float wsum = 0.f;
        #pragma unroll
        for (int w = 0; w < 8; ++w) wsum += wsump[w];
        float s = 0.f;
        #pragma unroll
        for (int w = 0; w < 8; ++w) s += haccp[w][tid];
        hv[tid] = s / wsum;
    }
    __syncthreads();

    // out = relu(hv @ W); thread t -> output column t
    if (tid < D_) {
        float o = 0.f;
        #pragma unroll 8
        for (int d = 0; d < D_; ++d) o += hv[d] * W[d * D_ + tid];
        out[b * D_ + tid] = fmaxf(o, 0.f);
    }
}

// ---------------------------------------------------------------------------
extern "C" void kernel_launch(void* const* d_in, const int* in_sizes, int n_in,
                              void* d_out, int out_size)
{
    const int*   seq  = (const int*)d_in[0];    // sequence       [B, L]
    const int*   last = (const int*)d_in[1];    // last_sequence  [B, L]
    const int*   seq1 = (const int*)d_in[2];    // sequence_1     [B, L1]
    const float* h1   = (const float*)d_in[3];  // hist_1         [B, L, D]
    const float* h2   = (const float*)d_in[4];  // hist_2         [B, L1, D]
    const float* W    = (const float*)d_in[5];  // W              [D, D]
    float* out = (float*)d_out;                 // [B, 1, D] fp32

    const size_t smemA = (size_t)(L_ * RS + L_ + L_ + 8 * 4 * L_ + 8 * D_) * sizeof(float)
                       + (size_t)L_ * sizeof(int);
    cudaFuncSetAttribute(self_attn_kernel,
                         cudaFuncAttributeMaxDynamicSharedMemorySize, (int)smemA);

    self_attn_kernel<<<B_, 256, smemA>>>(seq, last, h1);
    cross_kernel<<<B_, 256>>>(seq1, h2, W, out);
}

// round 5
// speedup vs baseline: 1.3129x; 1.3129x over previous
#include <cuda_runtime.h>
#include <cuda_bf16.h>
#include <cstdint>

#define B_   512
#define L_   256
#define D_   128
#define EPSF 0.01f
#define SRSB 272            // bf16 row stride in bytes (136 elems): ldmatrix conflict-free

// ---- smem byte offsets ----
#define SM_HH   0           // 256 x SRSB bf16 high split
#define SM_HL   69632       // low split
#define SM_INVB 139264      // 256 x float2 (inv_j, bias_j)
#define SM_SEL  141312      // 256 f32 (mask*last)
#define SM_VP   142336      // 8 x 256 f32 per-warp v partials
#define SM_DP   150528      // 8 x 128 f32 direct-term partials
#define SM_ACC  154624      // 256 f32
#define SM_TOT  155648
// cross-phase aliases (H region dead by then)
#define CX_HL   0
#define CX_WS   512
#define CX_HA   1024
#define CX_HV   5120
#define CX_IQ   5632

__device__ __forceinline__ uint32_t smem_u32(const void* p) {
    uint32_t a;
    asm("{ .reg .u64 t; cvta.to.shared.u64 t, %1; cvt.u32.u64 %0, t; }" : "=r"(a) : "l"(p));
    return a;
}
#define LDSM4(r, addr) \
    asm volatile("ldmatrix.sync.aligned.m8n8.x4.shared.b16 {%0,%1,%2,%3}, [%4];" \
        : "=r"((r)[0]), "=r"((r)[1]), "=r"((r)[2]), "=r"((r)[3]) : "r"(addr))
#define MMA16816(c, a, b0, b1) \
    asm volatile("mma.sync.aligned.m16n8k16.row.col.f32.bf16.bf16.f32 " \
        "{%0,%1,%2,%3}, {%4,%5,%6,%7}, {%8,%9}, {%0,%1,%2,%3};" \
        : "+f"((c)[0]), "+f"((c)[1]), "+f"((c)[2]), "+f"((c)[3]) \
        : "r"((a)[0]), "r"((a)[1]), "r"((a)[2]), "r"((a)[3]), "r"(b0), "r"(b1))

__global__ __launch_bounds__(256, 1)
void fused_itd(const int* __restrict__ seq, const int* __restrict__ last,
               const int* __restrict__ seq1, const float* __restrict__ h1,
               const float* __restrict__ h2, const float* __restrict__ W,
               float* __restrict__ out)
{
    extern __shared__ unsigned char smraw[];
    float* smf = (float*)smraw;
    unsigned char* smc = smraw;
    const uint32_t sb = smem_u32(smraw);
    const int b = blockIdx.x, tid = threadIdx.x, wid = tid >> 5, lane = tid & 31;

    // ---- masks / bias / zero-init ----
    {
        int sv = seq[b * L_ + tid], lv = last[b * L_ + tid];
        float m = (sv != 0) ? 1.f : 0.f;
        smf[SM_SEL / 4 + tid] = m * (float)lv;
        ((float*)(smc + SM_INVB))[tid * 2 + 1] = (sv != 0) ? 0.f : -1e4f;  // bias_j
    }
    for (int i = tid; i < 8 * 256; i += 256) smf[SM_VP / 4 + i] = 0.f;
    __syncthreads();

    // ---- load hist_1[b]: split to bf16 hi/lo, norms, direct sel*h term ----
    const float4* src4 = (const float4*)(h1 + (size_t)b * L_ * D_);
    const int d0 = lane * 4;
    float ds0 = 0.f, ds1 = 0.f, ds2 = 0.f, ds3 = 0.f;
    #pragma unroll 4
    for (int k = 0; k < 32; ++k) {
        const float4 v = src4[tid + k * 256];
        const int i = wid + 8 * k;                         // row (warp-uniform)
        float np = v.x * v.x + v.y * v.y + v.z * v.z + v.w * v.w;
        #pragma unroll
        for (int o = 16; o; o >>= 1) np += __shfl_xor_sync(0xffffffffu, np, o);
        if (lane == 0) ((float*)(smc + SM_INVB))[i * 2] = rsqrtf(np + EPSF);
        const float se = smf[SM_SEL / 4 + i];
        ds0 += se * v.x; ds1 += se * v.y; ds2 += se * v.z; ds3 += se * v.w;

        float xs[4] = { v.x, v.y, v.z, v.w };
        uint16_t hh[4], hl[4];
        #pragma unroll
        for (int j = 0; j < 4; ++j) {
            __nv_bfloat16 hb = __float2bfloat16_rn(xs[j]);
            __nv_bfloat16 lb = __float2bfloat16_rn(xs[j] - __bfloat162float(hb));
            hh[j] = __nv_bfloat16_raw(hb).x;
            hl[j] = __nv_bfloat16_raw(lb).x;
        }
        uint32_t off = (uint32_t)i * SRSB + (uint32_t)d0 * 2;
        *(uint2*)(smc + SM_HH + off) = make_uint2(
            (uint32_t)hh[0] | ((uint32_t)hh[1] << 16), (uint32_t)hh[2] | ((uint32_t)hh[3] << 16));
        *(uint2*)(smc + SM_HL + off) = make_uint2(
            (uint32_t)hl[0] | ((uint32_t)hl[1] << 16), (uint32_t)hl[2] | ((uint32_t)hl[3] << 16));
    }
    smf[SM_DP / 4 + wid * D_ + d0 + 0] = ds0;
    smf[SM_DP / 4 + wid * D_ + d0 + 1] = ds1;
    smf[SM_DP / 4 + wid * D_ + d0 + 2] = ds2;
    smf[SM_DP / 4 + wid * D_ + d0 + 3] = ds3;
    __syncthreads();

    // ---- self attention: S tiles via mma.sync, exp, v-reduction ----
    const uint32_t bAddrH = sb + SM_HH
        + (uint32_t)((lane & 7) + ((lane >> 4) * 8)) * SRSB + (uint32_t)((lane >> 3) & 1) * 16;
    const uint32_t bAddrL = bAddrH + (SM_HL - SM_HH);
    const float2* invb = (const float2*)(smc + SM_INVB);

    for (int g = 0; g < 2; ++g) {
        const int base = wid * 32 + g * 16;
        float acc[128];
        #pragma unroll
        for (int i = 0; i < 128; ++i) acc[i] = 0.f;

        const uint32_t aAddrH = sb + SM_HH
            + (uint32_t)(base + (lane & 7) + (((lane >> 3) & 1) * 8)) * SRSB
            + (uint32_t)((lane >> 4) * 8) * 2;
        const uint32_t aAddrL = aAddrH + (SM_HL - SM_HH);

        for (int k = 0; k < 8; ++k) {
            uint32_t ah[4], al[4];
            LDSM4(ah, aAddrH + k * 32);
            LDSM4(al, aAddrL + k * 32);
            #pragma unroll
            for (int nf = 0; nf < 16; ++nf) {
                uint32_t bh[4], bl[4];
                LDSM4(bh, bAddrH + nf * (16 * SRSB) + k * 32);
                MMA16816(&acc[8 * nf],     ah, bh[0], bh[1]);
                MMA16816(&acc[8 * nf + 4], ah, bh[2], bh[3]);
                MMA16816(&acc[8 * nf],     al, bh[0], bh[1]);
                MMA16816(&acc[8 * nf + 4], al, bh[2], bh[3]);
                LDSM4(bl, bAddrL + nf * (16 * SRSB) + k * 32);
                MMA16816(&acc[8 * nf],     ah, bl[0], bl[1]);
                MMA16816(&acc[8 * nf + 4], ah, bl[2], bl[3]);
            }
        }

        // exp(cos)*mask (bias form) + row sums; frag: c0:(r0,c) c1:(r0,c+1) c2:(r1,c) c3:(r1,c+1)
        const int r0 = base + (lane >> 2), r1 = r0 + 8;
        const float invi0 = invb[r0].x, invi1 = invb[r1].x;
        float ws0 = 0.f, ws1 = 0.f;
        #pragma unroll
        for (int f = 0; f < 32; ++f) {
            const int c0 = f * 8 + (lane & 3) * 2;
            const float2 ib0 = invb[c0], ib1 = invb[c0 + 1];
            float w00 = __expf(acc[4 * f + 0] * invi0 * ib0.x + ib0.y);
            float w01 = __expf(acc[4 * f + 1] * invi0 * ib1.x + ib1.y);
            float w10 = __expf(acc[4 * f + 2] * invi1 * ib0.x + ib0.y);
            float w11 = __expf(acc[4 * f + 3] * invi1 * ib1.x + ib1.y);
            acc[4 * f + 0] = w00; acc[4 * f + 1] = w01;
            acc[4 * f + 2] = w10; acc[4 * f + 3] = w11;
            ws0 += w00 + w01; ws1 += w10 + w11;
        }
        ws0 += __shfl_xor_sync(0xffffffffu, ws0, 1);
        ws0 += __shfl_xor_sync(0xffffffffu, ws0, 2);
        ws1 += __shfl_xor_sync(0xffffffffu, ws1, 1);
        ws1 += __shfl_xor_sync(0xffffffffu, ws1, 2);
        const float a0 = smf[SM_SEL / 4 + r0] / ws0;
        const float a1 = smf[SM_SEL / 4 + r1] / ws1;

        // v_j partial = a0*w[r0,j] + a1*w[r1,j], reduced over the 16 rows
        #pragma unroll
        for (int f = 0; f < 32; ++f) {
            float v0 = a0 * acc[4 * f + 0] + a1 * acc[4 * f + 2];
            float v1 = a0 * acc[4 * f + 1] + a1 * acc[4 * f + 3];
            #pragma unroll
            for (int o = 4; o <= 16; o <<= 1) {
                v0 += __shfl_xor_sync(0xffffffffu, v0, o);
                v1 += __shfl_xor_sync(0xffffffffu, v1, o);
            }
            if (lane < 4) {
                const int c0 = f * 8 + lane * 2;
                smf[SM_VP / 4 + wid * 256 + c0]     += v0;
                smf[SM_VP / 4 + wid * 256 + c0 + 1] += v1;
            }
        }
    }
    __syncthreads();

    // ---- v = sum of warp partials ----
    {
        float v = 0.f;
        #pragma unroll
        for (int w = 0; w < 8; ++w) v += smf[SM_VP / 4 + w * 256 + tid];
        smf[SM_VP / 4 + tid] = v;   // own slot only: no race
    }
    __syncthreads();

    // ---- acc[d] = sum_j v_j * (Hh[j,d] + Hl[j,d]) ----
    {
        const int d = tid & 127, jb = (tid >> 7) * 128;
        float a = 0.f;
        #pragma unroll 4
        for (int jj = 0; jj < 128; ++jj) {
            const int j = jb + jj;
            const float vj = smf[SM_VP / 4 + j];
            const uint32_t off = (uint32_t)j * SRSB + (uint32_t)d * 2;
            float hv = __bfloat162float(*(__nv_bfloat16*)(smc + SM_HH + off))
                     + __bfloat162float(*(__nv_bfloat16*)(smc + SM_HL + off));
            a += vj * hv;
        }
        smf[SM_ACC / 4 + tid] = a;
    }
    __syncthreads();
    if (tid < D_) {
        float s = smf[SM_ACC / 4 + tid] + smf[SM_ACC / 4 + 128 + tid];
        #pragma unroll
        for (int w = 0; w < 8; ++w) s += smf[SM_DP / 4 + w * D_ + tid];
        smf[SM_ACC / 4 + tid] = s;    // stash h_last out of the H region first
    }
    __syncthreads();
    if (tid < D_) smf[CX_HL / 4 + tid] = smf[SM_ACC / 4 + tid];  // H region now dead
    __syncthreads();

    // ---- cross cosine-attention over hist_2 + relu(h @ W) ----
    if (tid < 32) {
        float s = 0.f;
        #pragma unroll
        for (int c = 0; c < 4; ++c) { float v = smf[CX_HL / 4 + tid + 32 * c]; s += v * v; }
        #pragma unroll
        for (int o = 16; o; o >>= 1) s += __shfl_xor_sync(0xffffffffu, s, o);
        if (tid == 0) smf[CX_IQ / 4] = rsqrtf(s + EPSF);
    }
    __syncthreads();
    {
        const float invq = smf[CX_IQ / 4];
        const float* H2 = h2 + (size_t)b * 256 * D_;
        const float q0 = smf[CX_HL / 4 + lane * 4],     q1 = smf[CX_HL / 4 + lane * 4 + 1];
        const float q2 = smf[CX_HL / 4 + lane * 4 + 2], q3 = smf[CX_HL / 4 + lane * 4 + 3];
        float a0 = 0.f, a1 = 0.f, a2 = 0.f, a3 = 0.f, wp = 0.f;
        for (int k = wid; k < 256; k += 8) {
            float4 v = ((const float4*)(H2 + k * D_))[lane];
            float dot = v.x * q0 + v.y * q1 + v.z * q2 + v.w * q3;
            float nk  = v.x * v.x + v.y * v.y + v.z * v.z + v.w * v.w;
            #pragma unroll
            for (int o = 16; o; o >>= 1) {
                dot += __shfl_xor_sync(0xffffffffu, dot, o);
                nk  += __shfl_xor_sync(0xffffffffu, nk,  o);
            }
            float w = __expf(dot * rsqrtf(nk + EPSF) * invq)
                    * ((seq1[b * 256 + k] != 0) ? 1.f : 0.f);
            wp += w;
            a0 += w * v.x; a1 += w * v.y; a2 += w * v.z; a3 += w * v.w;
        }
        if (lane == 0) smf[CX_WS / 4 + wid] = wp;
        smf[CX_HA / 4 + wid * D_ + lane * 4]     = a0;
        smf[CX_HA / 4 + wid * D_ + lane * 4 + 1] = a1;
        smf[CX_HA / 4 + wid * D_ + lane * 4 + 2] = a2;
        smf[CX_HA / 4 + wid * D_ + lane * 4 + 3] = a3;
    }
    __syncthreads();
    if (tid < D_) {
        float ws = 0.f, s = 0.f;
        #pragma unroll
        for (int w = 0; w < 8; ++w) { ws += smf[CX_WS / 4 + w]; s += smf[CX_HA / 4 + w * D_ + tid]; }
        smf[CX_HV / 4 + tid] = s / ws;
    }
    __syncthreads();
    if (tid < D_) {
        float o = 0.f;
        #pragma unroll 8
        for (int d = 0; d < D_; ++d) o += smf[CX_HV / 4 + d] * W[d * D_ + tid];
        out[b * D_ + tid] = fmaxf(o, 0.f);
    }
}

extern "C" void kernel_launch(void* const* d_in, const int* in_sizes, int n_in,
                              void* d_out, int out_size)
{
    const int*   seq  = (const int*)d_in[0];
    const int*   last = (const int*)d_in[1];
    const int*   seq1 = (const int*)d_in[2];
    const float* h1   = (const float*)d_in[3];
    const float* h2   = (const float*)d_in[4];
    const float* W    = (const float*)d_in[5];
    float* out = (float*)d_out;

    cudaFuncSetAttribute(fused_itd, cudaFuncAttributeMaxDynamicSharedMemorySize, SM_TOT);
    fused_itd<<<B_, 256, SM_TOT>>>(seq, last, seq1, h1, h2, W, out);
}

// round 8
// speedup vs baseline: 2.2340x; 1.7016x over previous
#include <cuda_runtime.h>
#include <cuda_bf16.h>
#include <cstdint>

#define B_   512
#define L_   256
#define D_   128
#define EPSF 0.01f
#define SRSB 272            // bf16 row stride in bytes (136 elems): ldmatrix conflict-free
#define HLOFF 69632         // byte offset from HH to HL

// ---- smem byte offsets ----
#define SM_HH   0           // 256 x SRSB bf16 high split
#define SM_HL   69632       // low split
#define SM_INVB 139264      // 256 x float2 (inv_j, bias_j)
#define SM_SEL  141312      // 256 f32 (mask*last)
#define SM_WS   142336      // 256 x 2 f32 row-sum partials (per column half)
#define SM_VP   144384      // 16 x 256 f32 per-warp v partials
#define SM_DP   160768      // 16 x 128 f32 direct-term partials
#define SM_ACC  168960      // 512 f32
#define SM_TOT  171008
// cross-phase aliases (H region dead by then)
#define CX_HL   0
#define CX_WS   512
#define CX_HA   1024        // 16 x 128 f32
#define CX_HV   9216
#define CX_IQ   9728

__device__ __forceinline__ uint32_t smem_u32(const void* p) {
    uint32_t a;
    asm("{ .reg .u64 t; cvta.to.shared.u64 t, %1; cvt.u32.u64 %0, t; }" : "=r"(a) : "l"(p));
    return a;
}
#define LDSM4(r, addr) \
    asm volatile("ldmatrix.sync.aligned.m8n8.x4.shared.b16 {%0,%1,%2,%3}, [%4];" \
        : "=r"((r)[0]), "=r"((r)[1]), "=r"((r)[2]), "=r"((r)[3]) : "r"(addr))
#define MMA16816(c, a, b0, b1) \
    asm volatile("mma.sync.aligned.m16n8k16.row.col.f32.bf16.bf16.f32 " \
        "{%0,%1,%2,%3}, {%4,%5,%6,%7}, {%8,%9}, {%0,%1,%2,%3};" \
        : "+f"((c)[0]), "+f"((c)[1]), "+f"((c)[2]), "+f"((c)[3]) \
        : "r"((a)[0]), "r"((a)[1]), "r"((a)[2]), "r"((a)[3]), "r"(b0), "r"(b1))

__global__ __launch_bounds__(512, 1)
void fused_itd(const int* __restrict__ seq, const int* __restrict__ last,
               const int* __restrict__ seq1, const float* __restrict__ h1,
               const float* __restrict__ h2, const float* __restrict__ W,
               float* __restrict__ out)
{
    extern __shared__ unsigned char smraw[];
    float* smf = (float*)smraw;
    unsigned char* smc = smraw;
    const uint32_t sb = smem_u32(smraw);
    const int b = blockIdx.x, tid = threadIdx.x, wid = tid >> 5, lane = tid & 31;

    // ---- masks / bias / zero-init ----
    if (tid < 256) {
        int sv = seq[b * L_ + tid], lv = last[b * L_ + tid];
        float m = (sv != 0) ? 1.f : 0.f;
        smf[SM_SEL / 4 + tid] = m * (float)lv;
        ((float*)(smc + SM_INVB))[tid * 2 + 1] = (sv != 0) ? 0.f : -1e4f;  // bias_j
    }
    for (int i = tid; i < 16 * 256; i += 512) smf[SM_VP / 4 + i] = 0.f;
    __syncthreads();

    // ---- load hist_1[b]: split to bf16 hi/lo, norms, direct sel*h term ----
    const float4* src4 = (const float4*)(h1 + (size_t)b * L_ * D_);
    const int d0 = lane * 4;
    float ds0 = 0.f, ds1 = 0.f, ds2 = 0.f, ds3 = 0.f;
    #pragma unroll 4
    for (int k = 0; k < 16; ++k) {
        const float4 v = src4[tid + k * 512];
        const int i = wid + 16 * k;                        // row (warp-uniform)
        float np = v.x * v.x + v.y * v.y + v.z * v.z + v.w * v.w;
        #pragma unroll
        for (int o = 16; o; o >>= 1) np += __shfl_xor_sync(0xffffffffu, np, o);
        if (lane == 0) ((float*)(smc + SM_INVB))[i * 2] = rsqrtf(np + EPSF);
        const float se = smf[SM_SEL / 4 + i];
        ds0 += se * v.x; ds1 += se * v.y; ds2 += se * v.z; ds3 += se * v.w;

        float xs[4] = { v.x, v.y, v.z, v.w };
        uint16_t hh[4], hl[4];
        #pragma unroll
        for (int j = 0; j < 4; ++j) {
            __nv_bfloat16 hb = __float2bfloat16_rn(xs[j]);
            __nv_bfloat16 lb = __float2bfloat16_rn(xs[j] - __bfloat162float(hb));
            hh[j] = __nv_bfloat16_raw(hb).x;
            hl[j] = __nv_bfloat16_raw(lb).x;
        }
        uint32_t off = (uint32_t)i * SRSB + (uint32_t)d0 * 2;
        *(uint2*)(smc + SM_HH + off) = make_uint2(
            (uint32_t)hh[0] | ((uint32_t)hh[1] << 16), (uint32_t)hh[2] | ((uint32_t)hh[3] << 16));
        *(uint2*)(smc + SM_HL + off) = make_uint2(
            (uint32_t)hl[0] | ((uint32_t)hl[1] << 16), (uint32_t)hl[2] | ((uint32_t)hl[3] << 16));
    }
    smf[SM_DP / 4 + wid * D_ + d0 + 0] = ds0;
    smf[SM_DP / 4 + wid * D_ + d0 + 1] = ds1;
    smf[SM_DP / 4 + wid * D_ + d0 + 2] = ds2;
    smf[SM_DP / 4 + wid * D_ + d0 + 3] = ds3;
    __syncthreads();

    // ---- self attention: 32 jobs = 16 row-groups x 2 column halves ----
    // warp w: jobs {w, w+16} -> rg = job>>1 (w&1 fixed column half)
    const float2* invb = (const float2*)(smc + SM_INVB);
    const int half  = wid & 1;
    const int cbase = half * 128;
    const uint32_t bAddr = sb + SM_HH
        + (uint32_t)(cbase + (lane & 7) + ((lane >> 4) * 8)) * SRSB
        + (uint32_t)((lane >> 3) & 1) * 16;

    for (int jj = 0; jj < 2; ++jj) {
        const int rg = ((wid + jj * 16) >> 1);
        const int rbase = rg * 16;
        float acc[64];
        #pragma unroll
        for (int i = 0; i < 64; ++i) acc[i] = 0.f;

        const uint32_t aAddrH = sb + SM_HH
            + (uint32_t)(rbase + (lane & 7) + (((lane >> 3) & 1) * 8)) * SRSB
            + (uint32_t)((lane >> 4) * 8) * 2;
        const uint32_t aAddrL = aAddrH + HLOFF;

        for (int k = 0; k < 8; ++k) {
            uint32_t ah[4], al[4];
            LDSM4(ah, aAddrH + k * 32);
            LDSM4(al, aAddrL + k * 32);
            #pragma unroll
            for (int nf = 0; nf < 8; ++nf) {
                uint32_t bh[4], bl[4];
                LDSM4(bh, bAddr + nf * (16 * SRSB) + k * 32);
                MMA16816(&acc[8 * nf],     ah, bh[0], bh[1]);
                MMA16816(&acc[8 * nf + 4], ah, bh[2], bh[3]);
                MMA16816(&acc[8 * nf],     al, bh[0], bh[1]);
                MMA16816(&acc[8 * nf + 4], al, bh[2], bh[3]);
                LDSM4(bl, bAddr + HLOFF + nf * (16 * SRSB) + k * 32);
                MMA16816(&acc[8 * nf],     ah, bl[0], bl[1]);
                MMA16816(&acc[8 * nf + 4], ah, bl[2], bl[3]);
            }
        }

        // exp(cos)*mask (bias form); frag c0:(r0,c) c1:(r0,c+1) c2:(r1,c) c3:(r1,c+1)
        const int r0 = rbase + (lane >> 2), r1 = r0 + 8;
        const float invi0 = invb[r0].x, invi1 = invb[r1].x;
        float ws0 = 0.f, ws1 = 0.f;
        #pragma unroll
        for (int f = 0; f < 16; ++f) {
            const int c0 = cbase + f * 8 + (lane & 3) * 2;
            const float2 ib0 = invb[c0], ib1 = invb[c0 + 1];
            float w00 = __expf(acc[4 * f + 0] * invi0 * ib0.x + ib0.y);
            float w01 = __expf(acc[4 * f + 1] * invi0 * ib1.x + ib1.y);
            float w10 = __expf(acc[4 * f + 2] * invi1 * ib0.x + ib0.y);
            float w11 = __expf(acc[4 * f + 3] * invi1 * ib1.x + ib1.y);
            acc[4 * f + 0] = w00; acc[4 * f + 1] = w01;
            acc[4 * f + 2] = w10; acc[4 * f + 3] = w11;
            ws0 += w00 + w01; ws1 += w10 + w11;
        }
        ws0 += __shfl_xor_sync(0xffffffffu, ws0, 1);
        ws0 += __shfl_xor_sync(0xffffffffu, ws0, 2);
        ws1 += __shfl_xor_sync(0xffffffffu, ws1, 1);
        ws1 += __shfl_xor_sync(0xffffffffu, ws1, 2);
        if ((lane & 3) == 0) {
            smf[SM_WS / 4 + r0 * 2 + half] = ws0;
            smf[SM_WS / 4 + r1 * 2 + half] = ws1;
        }
        __syncthreads();   // both halves' row-sum partials visible

        const float a0 = smf[SM_SEL / 4 + r0]
                       / (smf[SM_WS / 4 + r0 * 2] + smf[SM_WS / 4 + r0 * 2 + 1]);
        const float a1 = smf[SM_SEL / 4 + r1]
                       / (smf[SM_WS / 4 + r1 * 2] + smf[SM_WS / 4 + r1 * 2 + 1]);

        // v_j partial = a0*w[r0,j] + a1*w[r1,j], reduced over this row-group
        #pragma unroll
        for (int f = 0; f < 16; ++f) {
            float v0 = a0 * acc[4 * f + 0] + a1 * acc[4 * f + 2];
            float v1 = a0 * acc[4 * f + 1] + a1 * acc[4 * f + 3];
            #pragma unroll
            for (int o = 4; o <= 16; o <<= 1) {
                v0 += __shfl_xor_sync(0xffffffffu, v0, o);
                v1 += __shfl_xor_sync(0xffffffffu, v1, o);
            }
            if (lane < 4) {
                const int c0 = cbase + f * 8 + lane * 2;
                smf[SM_VP / 4 + wid * 256 + c0]     += v0;
                smf[SM_VP / 4 + wid * 256 + c0 + 1] += v1;
            }
        }
    }
    __syncthreads();

    // ---- v = sum of warp partials (off-half slots are zero) ----
    if (tid < 256) {
        float v = 0.f;
        #pragma unroll
        for (int w = 0; w < 16; ++w) v += smf[SM_VP / 4 + w * 256 + tid];
        smf[SM_VP / 4 + tid] = v;   // own slot only: no race
    }
    __syncthreads();

    // ---- acc[d] = sum_j v_j * (Hh[j,d] + Hl[j,d]), 4-way split over j ----
    {
        const int d = tid & 127, jb = (tid >> 7) * 64;
        float a = 0.f;
        #pragma unroll 4
        for (int jx = 0; jx < 64; ++jx) {
            const int j = jb + jx;
            const float vj = smf[SM_VP / 4 + j];
            const uint32_t off = (uint32_t)j * SRSB + (uint32_t)d * 2;
            float hv = __bfloat162float(*(__nv_bfloat16*)(smc + SM_HH + off))
                     + __bfloat162float(*(__nv_bfloat16*)(smc + SM_HL + off));
            a += vj * hv;
        }
        smf[SM_ACC / 4 + tid] = a;
    }
    __syncthreads();
    if (tid < D_) {   // h_last -> CX_HL (H region dead after the sync above)
        float s = smf[SM_ACC / 4 + tid] + smf[SM_ACC / 4 + 128 + tid]
                + smf[SM_ACC / 4 + 256 + tid] + smf[SM_ACC / 4 + 384 + tid];
        #pragma unroll
        for (int w = 0; w < 16; ++w) s += smf[SM_DP / 4 + w * D_ + tid];
        smf[CX_HL / 4 + tid] = s;
    }
    __syncthreads();

    // ---- cross cosine-attention over hist_2 + relu(h @ W) ----
    if (tid < 32) {
        float s = 0.f;
        #pragma unroll
        for (int c = 0; c < 4; ++c) { float v = smf[CX_HL / 4 + tid + 32 * c]; s += v * v; }
        #pragma unroll
        for (int o = 16; o; o >>= 1) s += __shfl_xor_sync(0xffffffffu, s, o);
        if (tid == 0) smf[CX_IQ / 4] = rsqrtf(s + EPSF);
    }
    __syncthreads();
    {
        const float invq = smf[CX_IQ / 4];
        const float* H2 = h2 + (size_t)b * 256 * D_;
        const float q0 = smf[CX_HL / 4 + lane * 4],     q1 = smf[CX_HL / 4 + lane * 4 + 1];
        const float q2 = smf[CX_HL / 4 + lane * 4 + 2], q3 = smf[CX_HL / 4 + lane * 4 + 3];
        float a0 = 0.f, a1 = 0.f, a2 = 0.f, a3 = 0.f, wp = 0.f;
        for (int k = wid; k < 256; k += 16) {
            float4 v = ((const float4*)(H2 + k * D_))[lane];
            float dot = v.x * q0 + v.y * q1 + v.z * q2 + v.w * q3;
            float nk  = v.x * v.x + v.y * v.y + v.z * v.z + v.w * v.w;
            #pragma unroll
            for (int o = 16; o; o >>= 1) {
                dot += __shfl_xor_sync(0xffffffffu, dot, o);
                nk  += __shfl_xor_sync(0xffffffffu, nk,  o);
            }
            float w = __expf(dot * rsqrtf(nk + EPSF) * invq)
                    * ((seq1[b * 256 + k] != 0) ? 1.f : 0.f);
            wp += w;
            a0 += w * v.x; a1 += w * v.y; a2 += w * v.z; a3 += w * v.w;
        }
        if (lane == 0) smf[CX_WS / 4 + wid] = wp;
        smf[CX_HA / 4 + wid * D_ + lane * 4]     = a0;
        smf[CX_HA / 4 + wid * D_ + lane * 4 + 1] = a1;
        smf[CX_HA / 4 + wid * D_ + lane * 4 + 2] = a2;
        smf[CX_HA / 4 + wid * D_ + lane * 4 + 3] = a3;
    }
    __syncthreads();
    if (tid < D_) {
        float ws = 0.f, s = 0.f;
        #pragma unroll
        for (int w = 0; w < 16; ++w) { ws += smf[CX_WS / 4 + w]; s += smf[CX_HA / 4 + w * D_ + tid]; }
        smf[CX_HV / 4 + tid] = s / ws;
    }
    __syncthreads();
    if (tid < D_) {
        float o = 0.f;
        #pragma unroll 8
        for (int d = 0; d < D_; ++d) o += smf[CX_HV / 4 + d] * W[d * D_ + tid];
        out[b * D_ + tid] = fmaxf(o, 0.f);
    }
}

extern "C" void kernel_launch(void* const* d_in, const int* in_sizes, int n_in,
                              void* d_out, int out_size)
{
    const int*   seq  = (const int*)d_in[0];
    const int*   last = (const int*)d_in[1];
    const int*   seq1 = (const int*)d_in[2];
    const float* h1   = (const float*)d_in[3];
    const float* h2   = (const float*)d_in[4];
    const float* W    = (const float*)d_in[5];
    float* out = (float*)d_out;

    cudaFuncSetAttribute(fused_itd, cudaFuncAttributeMaxDynamicSharedMemorySize, SM_TOT);
    fused_itd<<<B_, 512, SM_TOT>>>(seq, last, seq1, h1, h2, W, out);
}

// round 9
// speedup vs baseline: 2.2897x; 1.0249x over previous
#include <cuda_runtime.h>
#include <cuda_bf16.h>
#include <cstdint>

#define B_   512
#define L_   256
#define D_   128
#define EPSF 0.01f
#define SRSB 272            // bf16 row stride in bytes: ldmatrix conflict-free
#define HLOFF 69632         // byte offset from HH to HL

// ---- smem byte offsets ----
#define SM_HH   0           // 256 x SRSB bf16 high split
#define SM_HL   69632       // low split
#define SM_INV  139264      // 256 f32
#define SM_M    140288      // 256 f32 key mask
#define SM_SEL  141312      // 256 f32 (mask*last)
#define SM_A    142336      // 256 f32 a_i = sel_i / wsum_i
#define SM_WSP  143360      // 16 x 256 f32 per-warp wsum partials
#define SM_VPT  159744      // 16 x 256 f32 per-warp v partials
#define SM_DP   176128      // 16 x 128 f32 direct-term partials
#define SM_ACC  184320      // 512 f32
#define SM_TOT  186368
// cross-phase aliases (H region dead by then)
#define CX_HL   0
#define CX_WS   512
#define CX_HA   1024        // 16 x 128 f32
#define CX_HV   9216
#define CX_IQ   9728

__device__ __forceinline__ uint32_t smem_u32(const void* p) {
    uint32_t a;
    asm("{ .reg .u64 t; cvta.to.shared.u64 t, %1; cvt.u32.u64 %0, t; }" : "=r"(a) : "l"(p));
    return a;
}
#define LDSM4(r, addr) \
    asm volatile("ldmatrix.sync.aligned.m8n8.x4.shared.b16 {%0,%1,%2,%3}, [%4];" \
        : "=r"((r)[0]), "=r"((r)[1]), "=r"((r)[2]), "=r"((r)[3]) : "r"(addr))
#define MMA16816(c, a, b0, b1) \
    asm volatile("mma.sync.aligned.m16n8k16.row.col.f32.bf16.bf16.f32 " \
        "{%0,%1,%2,%3}, {%4,%5,%6,%7}, {%8,%9}, {%0,%1,%2,%3};" \
        : "+f"((c)[0]), "+f"((c)[1]), "+f"((c)[2]), "+f"((c)[3]) \
        : "r"((a)[0]), "r"((a)[1]), "r"((a)[2]), "r"((a)[3]), "r"(b0), "r"(b1))
#define BFLY(x, o) x += __shfl_xor_sync(0xffffffffu, x, o)

__global__ __launch_bounds__(512, 1)
void fused_itd(const int* __restrict__ seq, const int* __restrict__ last,
               const int* __restrict__ seq1, const float* __restrict__ h1,
               const float* __restrict__ h2, const float* __restrict__ W,
               float* __restrict__ out)
{
    extern __shared__ unsigned char smraw[];
    float* smf = (float*)smraw;
    unsigned char* smc = smraw;
    const uint32_t sb = smem_u32(smraw);
    const int b = blockIdx.x, tid = threadIdx.x, wid = tid >> 5, lane = tid & 31;

    float* invv = smf + SM_INV / 4;
    float* mz   = smf + SM_M / 4;
    float* selv = smf + SM_SEL / 4;
    float* av   = smf + SM_A / 4;
    float* wsp  = smf + SM_WSP / 4;
    float* vpt  = smf + SM_VPT / 4;

    // ---- masks / zero-init of partial arrays ----
    if (tid < 256) {
        int sv = seq[b * L_ + tid], lv = last[b * L_ + tid];
        float m = (sv != 0) ? 1.f : 0.f;
        mz[tid]   = m;
        selv[tid] = m * (float)lv;
    }
    for (int i = tid; i < 2 * 16 * 256; i += 512) wsp[i] = 0.f;   // wsp + vpt contiguous
    __syncthreads();

    // ---- load hist_1[b]: split to bf16 hi/lo, norms, direct sel*h term ----
    const float4* src4 = (const float4*)(h1 + (size_t)b * L_ * D_);
    const int d0 = lane * 4;
    float ds0 = 0.f, ds1 = 0.f, ds2 = 0.f, ds3 = 0.f;
    #pragma unroll 4
    for (int k = 0; k < 16; ++k) {
        const float4 v = src4[tid + k * 512];
        const int i = wid + 16 * k;                        // row (warp-uniform)
        float np = v.x * v.x + v.y * v.y + v.z * v.z + v.w * v.w;
        #pragma unroll
        for (int o = 16; o; o >>= 1) np += __shfl_xor_sync(0xffffffffu, np, o);
        if (lane == 0) invv[i] = rsqrtf(np + EPSF);
        const float se = selv[i];
        ds0 += se * v.x; ds1 += se * v.y; ds2 += se * v.z; ds3 += se * v.w;

        float xs[4] = { v.x, v.y, v.z, v.w };
        uint16_t hh[4], hl[4];
        #pragma unroll
        for (int j = 0; j < 4; ++j) {
            __nv_bfloat16 hb = __float2bfloat16_rn(xs[j]);
            __nv_bfloat16 lb = __float2bfloat16_rn(xs[j] - __bfloat162float(hb));
            hh[j] = __nv_bfloat16_raw(hb).x;
            hl[j] = __nv_bfloat16_raw(lb).x;
        }
        uint32_t off = (uint32_t)i * SRSB + (uint32_t)d0 * 2;
        *(uint2*)(smc + SM_HH + off) = make_uint2(
            (uint32_t)hh[0] | ((uint32_t)hh[1] << 16), (uint32_t)hh[2] | ((uint32_t)hh[3] << 16));
        *(uint2*)(smc + SM_HL + off) = make_uint2(
            (uint32_t)hl[0] | ((uint32_t)hl[1] << 16), (uint32_t)hl[2] | ((uint32_t)hl[3] << 16));
    }
    smf[SM_DP / 4 + wid * D_ + d0 + 0] = ds0;
    smf[SM_DP / 4 + wid * D_ + d0 + 1] = ds1;
    smf[SM_DP / 4 + wid * D_ + d0 + 2] = ds2;
    smf[SM_DP / 4 + wid * D_ + d0 + 3] = ds3;
    __syncthreads();

    // =======================================================================
    // Self attention on upper-triangular 16x16 tiles (136 jobs, 16 warps).
    // Warp w takes jobs w, w+16, ..., keeps e-tiles in registers across the
    // wsum barrier. Tile (tr,tc): e_rc = exp(cos_rc), symmetric.
    // =======================================================================
    float et[72];

    // ---- phase 1: MMA + exp + wsum contributions (rows direct, cols mirror) ----
    #pragma unroll
    for (int t = 0; t < 9; ++t) {
        const int j = wid + 16 * t;
        if (j < 136) {
            int tr = 0, rem = j;
            while (rem >= 16 - tr) { rem -= 16 - tr; ++tr; }
            const int tc = tr + rem;
            float* acc = &et[8 * t];
            #pragma unroll
            for (int i = 0; i < 8; ++i) acc[i] = 0.f;

            const uint32_t aH = sb + SM_HH
                + (uint32_t)(tr * 16 + (lane & 7) + (((lane >> 3) & 1) * 8)) * SRSB
                + (uint32_t)((lane >> 4) * 8) * 2;
            const uint32_t bH = sb + SM_HH
                + (uint32_t)(tc * 16 + (lane & 7) + ((lane >> 4) * 8)) * SRSB
                + (uint32_t)((lane >> 3) & 1) * 16;

            for (int k = 0; k < 8; ++k) {
                uint32_t ah[4], al[4], bh[4], bl[4];
                LDSM4(ah, aH + k * 32);
                LDSM4(al, aH + HLOFF + k * 32);
                LDSM4(bh, bH + k * 32);
                MMA16816(acc,     ah, bh[0], bh[1]);
                MMA16816(acc + 4, ah, bh[2], bh[3]);
                MMA16816(acc,     al, bh[0], bh[1]);
                MMA16816(acc + 4, al, bh[2], bh[3]);
                LDSM4(bl, bH + HLOFF + k * 32);
                MMA16816(acc,     ah, bl[0], bl[1]);
                MMA16816(acc + 4, ah, bl[2], bl[3]);
            }

            // frag map: acc[0]:(r0,c0) [1]:(r0,c0+1) [2]:(r1,c0) [3]:(r1,c0+1)
            //           acc[4..7]: same rows, cols c0+8 / c0+9
            const int r0 = tr * 16 + (lane >> 2), r1 = r0 + 8;
            const int c0 = tc * 16 + (lane & 3) * 2;
            const float ir0 = invv[r0], ir1 = invv[r1];
            const float ic0 = invv[c0], ic1 = invv[c0 + 1];
            const float ic8 = invv[c0 + 8], ic9 = invv[c0 + 9];
            acc[0] = __expf(acc[0] * ir0 * ic0); acc[1] = __expf(acc[1] * ir0 * ic1);
            acc[2] = __expf(acc[2] * ir1 * ic0); acc[3] = __expf(acc[3] * ir1 * ic1);
            acc[4] = __expf(acc[4] * ir0 * ic8); acc[5] = __expf(acc[5] * ir0 * ic9);
            acc[6] = __expf(acc[6] * ir1 * ic8); acc[7] = __expf(acc[7] * ir1 * ic9);

            // direct: ws[r] += sum_c e*m_c
            const float mc0 = mz[c0], mc1 = mz[c0 + 1], mc8 = mz[c0 + 8], mc9 = mz[c0 + 9];
            float rs0 = acc[0] * mc0 + acc[1] * mc1 + acc[4] * mc8 + acc[5] * mc9;
            float rs1 = acc[2] * mc0 + acc[3] * mc1 + acc[6] * mc8 + acc[7] * mc9;
            BFLY(rs0, 1); BFLY(rs0, 2);
            BFLY(rs1, 1); BFLY(rs1, 2);
            if ((lane & 3) == 0) {
                wsp[wid * 256 + r0] += rs0;
                wsp[wid * 256 + r1] += rs1;
            }
            // mirror: ws[c] += sum_r e*m_r  (skip on diagonal tiles)
            if (tr != tc) {
                const float mr0 = mz[r0], mr1 = mz[r1];
                float cs0 = acc[0] * mr0 + acc[2] * mr1;
                float cs1 = acc[1] * mr0 + acc[3] * mr1;
                float cs8 = acc[4] * mr0 + acc[6] * mr1;
                float cs9 = acc[5] * mr0 + acc[7] * mr1;
                BFLY(cs0, 4); BFLY(cs0, 8); BFLY(cs0, 16);
                BFLY(cs1, 4); BFLY(cs1, 8); BFLY(cs1, 16);
                BFLY(cs8, 4); BFLY(cs8, 8); BFLY(cs8, 16);
                BFLY(cs9, 4); BFLY(cs9, 8); BFLY(cs9, 16);
                if (lane < 4) {
                    const int cb = tc * 16 + lane * 2;
                    wsp[wid * 256 + cb]     += cs0;
                    wsp[wid * 256 + cb + 1] += cs1;
                    wsp[wid * 256 + cb + 8] += cs8;
                    wsp[wid * 256 + cb + 9] += cs9;
                }
            }
        }
    }
    __syncthreads();

    // ---- a_i = sel_i / wsum_i ----
    if (tid < 256) {
        float ws = 0.f;
        #pragma unroll
        for (int w = 0; w < 16; ++w) ws += wsp[w * 256 + tid];
        av[tid] = selv[tid] / ws;
    }
    __syncthreads();

    // ---- phase 2: v contributions (cols direct, rows mirror) ----
    #pragma unroll
    for (int t = 0; t < 9; ++t) {
        const int j = wid + 16 * t;
        if (j < 136) {
            int tr = 0, rem = j;
            while (rem >= 16 - tr) { rem -= 16 - tr; ++tr; }
            const int tc = tr + rem;
            const float* e = &et[8 * t];
            const int r0 = tr * 16 + (lane >> 2), r1 = r0 + 8;
            const int c0 = tc * 16 + (lane & 3) * 2;

            // direct: v[c] += m_c * sum_r a_r e_rc
            const float ar0 = av[r0], ar1 = av[r1];
            float pc0 = ar0 * e[0] + ar1 * e[2];
            float pc1 = ar0 * e[1] + ar1 * e[3];
            float pc8 = ar0 * e[4] + ar1 * e[6];
            float pc9 = ar0 * e[5] + ar1 * e[7];
            BFLY(pc0, 4); BFLY(pc0, 8); BFLY(pc0, 16);
            BFLY(pc1, 4); BFLY(pc1, 8); BFLY(pc1, 16);
            BFLY(pc8, 4); BFLY(pc8, 8); BFLY(pc8, 16);
            BFLY(pc9, 4); BFLY(pc9, 8); BFLY(pc9, 16);
            if (lane < 4) {
                const int cb = tc * 16 + lane * 2;
                vpt[wid * 256 + cb]     += pc0 * mz[cb];
                vpt[wid * 256 + cb + 1] += pc1 * mz[cb + 1];
                vpt[wid * 256 + cb + 8] += pc8 * mz[cb + 8];
                vpt[wid * 256 + cb + 9] += pc9 * mz[cb + 9];
            }
            // mirror: v[r] += m_r * sum_c a_c e_rc  (skip on diagonal tiles)
            if (tr != tc) {
                const float ac0 = av[c0], ac1 = av[c0 + 1];
                const float ac8 = av[c0 + 8], ac9 = av[c0 + 9];
                float qr0 = ac0 * e[0] + ac1 * e[1] + ac8 * e[4] + ac9 * e[5];
                float qr1 = ac0 * e[2] + ac1 * e[3] + ac8 * e[6] + ac9 * e[7];
                BFLY(qr0, 1); BFLY(qr0, 2);
                BFLY(qr1, 1); BFLY(qr1, 2);
                if ((lane & 3) == 0) {
                    vpt[wid * 256 + r0] += qr0 * mz[r0];
                    vpt[wid * 256 + r1] += qr1 * mz[r1];
                }
            }
        }
    }
    __syncthreads();

    // ---- v = sum of warp partials ----
    if (tid < 256) {
        float v = 0.f;
        #pragma unroll
        for (int w = 0; w < 16; ++w) v += vpt[w * 256 + tid];
        vpt[tid] = v;   // own slot only: no race
    }
    __syncthreads();

    // ---- acc[d] = sum_j v_j * (Hh[j,d] + Hl[j,d]), 4-way split over j ----
    {
        const int d = tid & 127, jb = (tid >> 7) * 64;
        float a = 0.f;
        #pragma unroll 4
        for (int jx = 0; jx < 64; ++jx) {
            const int j = jb + jx;
            const float vj = vpt[j];
            const uint32_t off = (uint32_t)j * SRSB + (uint32_t)d * 2;
            float hv = __bfloat162float(*(__nv_bfloat16*)(smc + SM_HH + off))
                     + __bfloat162float(*(__nv_bfloat16*)(smc + SM_HL + off));
            a += vj * hv;
        }
        smf[SM_ACC / 4 + tid] = a;
    }
    __syncthreads();
    if (tid < D_) {   // h_last -> CX_HL (H region dead after the sync above)
        float s = smf[SM_ACC / 4 + tid] + smf[SM_ACC / 4 + 128 + tid]
                + smf[SM_ACC / 4 + 256 + tid] + smf[SM_ACC / 4 + 384 + tid];
        #pragma unroll
        for (int w = 0; w < 16; ++w) s += smf[SM_DP / 4 + w * D_ + tid];
        smf[CX_HL / 4 + tid] = s;
    }
    __syncthreads();

    // ---- cross cosine-attention over hist_2 + relu(h @ W) ----
    if (tid < 32) {
        float s = 0.f;
        #pragma unroll
        for (int c = 0; c < 4; ++c) { float v = smf[CX_HL / 4 + tid + 32 * c]; s += v * v; }
        #pragma unroll
        for (int o = 16; o; o >>= 1) s += __shfl_xor_sync(0xffffffffu, s, o);
        if (tid == 0) smf[CX_IQ / 4] = rsqrtf(s + EPSF);
    }
    __syncthreads();
    {
        const float invq = smf[CX_IQ / 4];
        const float* H2 = h2 + (size_t)b * 256 * D_;
        const float q0 = smf[CX_HL / 4 + lane * 4],     q1 = smf[CX_HL / 4 + lane * 4 + 1];
        const float q2 = smf[CX_HL / 4 + lane * 4 + 2], q3 = smf[CX_HL / 4 + lane * 4 + 3];
        float a0 = 0.f, a1 = 0.f, a2 = 0.f, a3 = 0.f, wp = 0.f;
        for (int k = wid; k < 256; k += 16) {
            float4 v = ((const float4*)(H2 + k * D_))[lane];
            float dot = v.x * q0 + v.y * q1 + v.z * q2 + v.w * q3;
            float nk  = v.x * v.x + v.y * v.y + v.z * v.z + v.w * v.w;
            #pragma unroll
            for (int o = 16; o; o >>= 1) {
                dot += __shfl_xor_sync(0xffffffffu, dot, o);
                nk  += __shfl_xor_sync(0xffffffffu, nk,  o);
            }
            float w = __expf(dot * rsqrtf(nk + EPSF) * invq)
                    * ((seq1[b * 256 + k] != 0) ? 1.f : 0.f);
            wp += w;
            a0 += w * v.x; a1 += w * v.y; a2 += w * v.z; a3 += w * v.w;
        }
        if (lane == 0) smf[CX_WS / 4 + wid] = wp;
        smf[CX_HA / 4 + wid * D_ + lane * 4]     = a0;
        smf[CX_HA / 4 + wid * D_ + lane * 4 + 1] = a1;
        smf[CX_HA / 4 + wid * D_ + lane * 4 + 2] = a2;
        smf[CX_HA / 4 + wid * D_ + lane * 4 + 3] = a3;
    }
    __syncthreads();
    if (tid < D_) {
        float ws = 0.f, s = 0.f;
        #pragma unroll
        for (int w = 0; w < 16; ++w) { ws += smf[CX_WS / 4 + w]; s += smf[CX_HA / 4 + w * D_ + tid]; }
        smf[CX_HV / 4 + tid] = s / ws;
    }
    __syncthreads();
    if (tid < D_) {
        float o = 0.f;
        #pragma unroll 8
        for (int d = 0; d < D_; ++d) o += smf[CX_HV / 4 + d] * W[d * D_ + tid];
        out[b * D_ + tid] = fmaxf(o, 0.f);
    }
}

extern "C" void kernel_launch(void* const* d_in, const int* in_sizes, int n_in,
                              void* d_out, int out_size)
{
    const int*   seq  = (const int*)d_in[0];
    const int*   last = (const int*)d_in[1];
    const int*   seq1 = (const int*)d_in[2];
    const float* h1   = (const float*)d_in[3];
    const float* h2   = (const float*)d_in[4];
    const float* W    = (const float*)d_in[5];
    float* out = (float*)d_out;

    cudaFuncSetAttribute(fused_itd, cudaFuncAttributeMaxDynamicSharedMemorySize, SM_TOT);
    fused_itd<<<B_, 512, SM_TOT>>>(seq, last, seq1, h1, h2, W, out);
}

// round 11
// speedup vs baseline: 2.3524x; 1.0274x over previous
#include <cuda_runtime.h>
#include <cuda_bf16.h>
#include <cstdint>

#define B_   512
#define L_   256
#define D_   128
#define EPSF 0.01f
#define SRSB 272            // bf16 row stride in bytes: ldmatrix conflict-free
#define HLOFF 69632         // byte offset from HH to HL

// ---- smem byte offsets ----
#define SM_HH   0           // 256 x SRSB bf16 high split
#define SM_HL   69632       // low split
#define SM_INV  139264      // 256 f32
#define SM_M    140288      // 256 f32 key mask
#define SM_SEL  141312      // 256 f32 (mask*last)
#define SM_A    142336      // 256 f32 a_i = sel_i / wsum_i
#define SM_WSP  143360      // 16 x 256 f32 per-warp wsum partials
#define SM_VPT  159744      // 16 x 256 f32 per-warp v partials
#define SM_DP   176128      // 16 x 128 f32 direct-term partials
#define SM_ACC  184320      // 512 f32
#define SM_TOT  186368
// cross-phase aliases (H region dead by then)
#define CX_HL   0
#define CX_WS   512
#define CX_HA   1024        // 16 x 128 f32
#define CX_HV   9216
#define CX_IQ   9728

// packed (tr<<4 | tc) for upper-triangular job index j in [0,136)
__device__ __constant__ unsigned char TRTAB[136] = {
    0x00,0x01,0x02,0x03,0x04,0x05,0x06,0x07,0x08,0x09,0x0A,0x0B,0x0C,0x0D,0x0E,0x0F,
    0x11,0x12,0x13,0x14,0x15,0x16,0x17,0x18,0x19,0x1A,0x1B,0x1C,0x1D,0x1E,0x1F,
    0x22,0x23,0x24,0x25,0x26,0x27,0x28,0x29,0x2A,0x2B,0x2C,0x2D,0x2E,0x2F,
    0x33,0x34,0x35,0x36,0x37,0x38,0x39,0x3A,0x3B,0x3C,0x3D,0x3E,0x3F,
    0x44,0x45,0x46,0x47,0x48,0x49,0x4A,0x4B,0x4C,0x4D,0x4E,0x4F,
    0x55,0x56,0x57,0x58,0x59,0x5A,0x5B,0x5C,0x5D,0x5E,0x5F,
    0x66,0x67,0x68,0x69,0x6A,0x6B,0x6C,0x6D,0x6E,0x6F,
    0x77,0x78,0x79,0x7A,0x7B,0x7C,0x7D,0x7E,0x7F,
    0x88,0x89,0x8A,0x8B,0x8C,0x8D,0x8E,0x8F,
    0x99,0x9A,0x9B,0x9C,0x9D,0x9E,0x9F,
    0xAA,0xAB,0xAC,0xAD,0xAE,0xAF,
    0xBB,0xBC,0xBD,0xBE,0xBF,
    0xCC,0xCD,0xCE,0xCF,
    0xDD,0xDE,0xDF,
    0xEE,0xEF,
    0xFF
};

__device__ __forceinline__ uint32_t smem_u32(const void* p) {
    uint32_t a;
    asm("{ .reg .u64 t; cvta.to.shared.u64 t, %1; cvt.u32.u64 %0, t; }" : "=r"(a) : "l"(p));
    return a;
}
#define LDSM4(r, addr) \
    asm volatile("ldmatrix.sync.aligned.m8n8.x4.shared.b16 {%0,%1,%2,%3}, [%4];" \
        : "=r"((r)[0]), "=r"((r)[1]), "=r"((r)[2]), "=r"((r)[3]) : "r"(addr))
#define MMA16816(c, a, b0, b1) \
    asm volatile("mma.sync.aligned.m16n8k16.row.col.f32.bf16.bf16.f32 " \
        "{%0,%1,%2,%3}, {%4,%5,%6,%7}, {%8,%9}, {%0,%1,%2,%3};" \
        : "+f"((c)[0]), "+f"((c)[1]), "+f"((c)[2]), "+f"((c)[3]) \
        : "r"((a)[0]), "r"((a)[1]), "r"((a)[2]), "r"((a)[3]), "r"(b0), "r"(b1))
#define BFLY(x, o) x += __shfl_xor_sync(0xffffffffu, x, o)

__global__ __launch_bounds__(512, 1)
void fused_itd(const int* __restrict__ seq, const int* __restrict__ last,
               const int* __restrict__ seq1, const float* __restrict__ h1,
               const float* __restrict__ h2, const float* __restrict__ W,
               float* __restrict__ out)
{
    extern __shared__ unsigned char smraw[];
    float* smf = (float*)smraw;
    unsigned char* smc = smraw;
    const uint32_t sb = smem_u32(smraw);
    const int b = blockIdx.x, tid = threadIdx.x, wid = tid >> 5, lane = tid & 31;

    float* invv = smf + SM_INV / 4;
    float* mz   = smf + SM_M / 4;
    float* selv = smf + SM_SEL / 4;
    float* av   = smf + SM_A / 4;
    float* wsp  = smf + SM_WSP / 4;
    float* vpt  = smf + SM_VPT / 4;

    // ---- masks / zero-init of partial arrays ----
    if (tid < 256) {
        int sv = seq[b * L_ + tid], lv = last[b * L_ + tid];
        float m = (sv != 0) ? 1.f : 0.f;
        mz[tid]   = m;
        selv[tid] = m * (float)lv;
    }
    for (int i = tid; i < 2 * 16 * 256; i += 512) wsp[i] = 0.f;   // wsp + vpt contiguous
    __syncthreads();

    // ---- load hist_1[b]: split to bf16 hi/lo, norms, direct sel*h term ----
    const float4* src4 = (const float4*)(h1 + (size_t)b * L_ * D_);
    const int d0 = lane * 4;
    float ds0 = 0.f, ds1 = 0.f, ds2 = 0.f, ds3 = 0.f;
    #pragma unroll 4
    for (int k = 0; k < 16; ++k) {
        const float4 v = src4[tid + k * 512];
        const int i = wid + 16 * k;                        // row (warp-uniform)
        float np = v.x * v.x + v.y * v.y + v.z * v.z + v.w * v.w;
        #pragma unroll
        for (int o = 16; o; o >>= 1) np += __shfl_xor_sync(0xffffffffu, np, o);
        if (lane == 0) invv[i] = rsqrtf(np + EPSF);
        const float se = selv[i];
        ds0 += se * v.x; ds1 += se * v.y; ds2 += se * v.z; ds3 += se * v.w;

        float xs[4] = { v.x, v.y, v.z, v.w };
        uint16_t hh[4], hl[4];
        #pragma unroll
        for (int j = 0; j < 4; ++j) {
            __nv_bfloat16 hb = __float2bfloat16_rn(xs[j]);
            __nv_bfloat16 lb = __float2bfloat16_rn(xs[j] - __bfloat162float(hb));
            hh[j] = __nv_bfloat16_raw(hb).x;
            hl[j] = __nv_bfloat16_raw(lb).x;
        }
        uint32_t off = (uint32_t)i * SRSB + (uint32_t)d0 * 2;
        *(uint2*)(smc + SM_HH + off) = make_uint2(
            (uint32_t)hh[0] | ((uint32_t)hh[1] << 16), (uint32_t)hh[2] | ((uint32_t)hh[3] << 16));
        *(uint2*)(smc + SM_HL + off) = make_uint2(
            (uint32_t)hl[0] | ((uint32_t)hl[1] << 16), (uint32_t)hl[2] | ((uint32_t)hl[3] << 16));
    }
    smf[SM_DP / 4 + wid * D_ + d0 + 0] = ds0;
    smf[SM_DP / 4 + wid * D_ + d0 + 1] = ds1;
    smf[SM_DP / 4 + wid * D_ + d0 + 2] = ds2;
    smf[SM_DP / 4 + wid * D_ + d0 + 3] = ds3;
    __syncthreads();

    // =======================================================================
    // Self attention on upper-triangular 16x16 tiles (136 jobs, 16 warps).
    // Warp w takes jobs w, w+16, ..., keeps e-tiles in registers across the
    // wsum barrier. Three independent accumulator sets per tile -> 6 MMA chains.
    // =======================================================================
    float et[72];

    // ---- phase 1: MMA + exp + wsum contributions (rows direct, cols mirror) ----
    #pragma unroll
    for (int t = 0; t < 9; ++t) {
        const int j = wid + 16 * t;
        if (j < 136) {
            const int pk = TRTAB[j];
            const int tr = pk >> 4, tc = pk & 15;
            float* acc = &et[8 * t];
            float a1r[8], a2r[8];
            #pragma unroll
            for (int i = 0; i < 8; ++i) { acc[i] = 0.f; a1r[i] = 0.f; a2r[i] = 0.f; }

            const uint32_t aH = sb + SM_HH
                + (uint32_t)(tr * 16 + (lane & 7) + (((lane >> 3) & 1) * 8)) * SRSB
                + (uint32_t)((lane >> 4) * 8) * 2;
            const uint32_t bH = sb + SM_HH
                + (uint32_t)(tc * 16 + (lane & 7) + ((lane >> 4) * 8)) * SRSB
                + (uint32_t)((lane >> 3) & 1) * 16;

            #pragma unroll 2
            for (int k = 0; k < 8; ++k) {
                uint32_t ah[4], al[4], bh[4], bl[4];
                LDSM4(ah, aH + k * 32);
                LDSM4(al, aH + HLOFF + k * 32);
                LDSM4(bh, bH + k * 32);
                LDSM4(bl, bH + HLOFF + k * 32);
                MMA16816(acc,     ah, bh[0], bh[1]);
                MMA16816(acc + 4, ah, bh[2], bh[3]);
                MMA16816(a1r,     al, bh[0], bh[1]);
                MMA16816(a1r + 4, al, bh[2], bh[3]);
                MMA16816(a2r,     ah, bl[0], bl[1]);
                MMA16816(a2r + 4, ah, bl[2], bl[3]);
            }
            #pragma unroll
            for (int i = 0; i < 8; ++i) acc[i] += a1r[i] + a2r[i];

            // frag map: acc[0]:(r0,c0) [1]:(r0,c0+1) [2]:(r1,c0) [3]:(r1,c0+1)
            //           acc[4..7]: same rows, cols c0+8 / c0+9
            const int r0 = tr * 16 + (lane >> 2), r1 = r0 + 8;
            const int c0 = tc * 16 + (lane & 3) * 2;
            const float ir0 = invv[r0], ir1 = invv[r1];
            const float ic0 = invv[c0], ic1 = invv[c0 + 1];
            const float ic8 = invv[c0 + 8], ic9 = invv[c0 + 9];
            acc[0] = __expf(acc[0] * ir0 * ic0); acc[1] = __expf(acc[1] * ir0 * ic1);
            acc[2] = __expf(acc[2] * ir1 * ic0); acc[3] = __expf(acc[3] * ir1 * ic1);
            acc[4] = __expf(acc[4] * ir0 * ic8); acc[5] = __expf(acc[5] * ir0 * ic9);
            acc[6] = __expf(acc[6] * ir1 * ic8); acc[7] = __expf(acc[7] * ir1 * ic9);

            // direct: ws[r] += sum_c e*m_c
            const float mc0 = mz[c0], mc1 = mz[c0 + 1], mc8 = mz[c0 + 8], mc9 = mz[c0 + 9];
            float rs0 = acc[0] * mc0 + acc[1] * mc1 + acc[4] * mc8 + acc[5] * mc9;
            float rs1 = acc[2] * mc0 + acc[3] * mc1 + acc[6] * mc8 + acc[7] * mc9;
            BFLY(rs0, 1); BFLY(rs0, 2);
            BFLY(rs1, 1); BFLY(rs1, 2);
            if ((lane & 3) == 0) {
                wsp[wid * 256 + r0] += rs0;
                wsp[wid * 256 + r1] += rs1;
            }
            // mirror: ws[c] += sum_r e*m_r  (skip on diagonal tiles)
            if (tr != tc) {
                const float mr0 = mz[r0], mr1 = mz[r1];
                float cs0 = acc[0] * mr0 + acc[2] * mr1;
                float cs1 = acc[1] * mr0 + acc[3] * mr1;
                float cs8 = acc[4] * mr0 + acc[6] * mr1;
                float cs9 = acc[5] * mr0 + acc[7] * mr1;
                BFLY(cs0, 4); BFLY(cs0, 8); BFLY(cs0, 16);
                BFLY(cs1, 4); BFLY(cs1, 8); BFLY(cs1, 16);
                BFLY(cs8, 4); BFLY(cs8, 8); BFLY(cs8, 16);
                BFLY(cs9, 4); BFLY(cs9, 8); BFLY(cs9, 16);
                if (lane < 4) {
                    const int cb = tc * 16 + lane * 2;
                    wsp[wid * 256 + cb]     += cs0;
                    wsp[wid * 256 + cb + 1] += cs1;
                    wsp[wid * 256 + cb + 8] += cs8;
                    wsp[wid * 256 + cb + 9] += cs9;
                }
            }
        }
    }
    __syncthreads();

    // ---- a_i = sel_i / wsum_i ----
    if (tid < 256) {
        float ws = 0.f;
        #pragma unroll
        for (int w = 0; w < 16; ++w) ws += wsp[w * 256 + tid];
        av[tid] = selv[tid] / ws;
    }
    __syncthreads();

    // ---- phase 2: v contributions (cols direct, rows mirror) ----
    #pragma unroll
    for (int t = 0; t < 9; ++t) {
        const int j = wid + 16 * t;
        if (j < 136) {
            const int pk = TRTAB[j];
            const int tr = pk >> 4, tc = pk & 15;
            const float* e = &et[8 * t];
            const int r0 = tr * 16 + (lane >> 2), r1 = r0 + 8;
            const int c0 = tc * 16 + (lane & 3) * 2;

            // direct: v[c] += m_c * sum_r a_r e_rc
            const float ar0 = av[r0], ar1 = av[r1];
            float pc0 = ar0 * e[0] + ar1 * e[2];
            float pc1 = ar0 * e[1] + ar1 * e[3];
            float pc8 = ar0 * e[4] + ar1 * e[6];
            float pc9 = ar0 * e[5] + ar1 * e[7];
            BFLY(pc0, 4); BFLY(pc0, 8); BFLY(pc0, 16);
            BFLY(pc1, 4); BFLY(pc1, 8); BFLY(pc1, 16);
            BFLY(pc8, 4); BFLY(pc8, 8); BFLY(pc8, 16);
            BFLY(pc9, 4); BFLY(pc9, 8); BFLY(pc9, 16);
            if (lane < 4) {
                const int cb = tc * 16 + lane * 2;
                vpt[wid * 256 + cb]     += pc0 * mz[cb];
                vpt[wid * 256 + cb + 1] += pc1 * mz[cb + 1];
                vpt[wid * 256 + cb + 8] += pc8 * mz[cb + 8];
                vpt[wid * 256 + cb + 9] += pc9 * mz[cb + 9];
            }
            // mirror: v[r] += m_r * sum_c a_c e_rc  (skip on diagonal tiles)
            if (tr != tc) {
                const float ac0 = av[c0], ac1 = av[c0 + 1];
                const float ac8 = av[c0 + 8], ac9 = av[c0 + 9];
                float qr0 = ac0 * e[0] + ac1 * e[1] + ac8 * e[4] + ac9 * e[5];
                float qr1 = ac0 * e[2] + ac1 * e[3] + ac8 * e[6] + ac9 * e[7];
                BFLY(qr0, 1); BFLY(qr0, 2);
                BFLY(qr1, 1); BFLY(qr1, 2);
                if ((lane & 3) == 0) {
                    vpt[wid * 256 + r0] += qr0 * mz[r0];
                    vpt[wid * 256 + r1] += qr1 * mz[r1];
                }
            }
        }
    }
    __syncthreads();

    // ---- v = sum of warp partials ----
    if (tid < 256) {
        float v = 0.f;
        #pragma unroll
        for (int w = 0; w < 16; ++w) v += vpt[w * 256 + tid];
        vpt[tid] = v;   // own slot only: no race
    }
    __syncthreads();

    // ---- acc[d] = sum_j v_j * (Hh[j,d] + Hl[j,d]), 4-way split over j ----
    {
        const int d = tid & 127, jb = (tid >> 7) * 64;
        float a = 0.f;
        #pragma unroll 4
        for (int jx = 0; jx < 64; ++jx) {
            const int j = jb + jx;
            const float vj = vpt[j];
            const uint32_t off = (uint32_t)j * SRSB + (uint32_t)d * 2;
            float hv = __bfloat162float(*(__nv_bfloat16*)(smc + SM_HH + off))
                     + __bfloat162float(*(__nv_bfloat16*)(smc + SM_HL + off));
            a += vj * hv;
        }
        smf[SM_ACC / 4 + tid] = a;
    }
    __syncthreads();
    if (tid < D_) {   // h_last -> CX_HL (H region dead after the sync above)
        float s = smf[SM_ACC / 4 + tid] + smf[SM_ACC / 4 + 128 + tid]
                + smf[SM_ACC / 4 + 256 + tid] + smf[SM_ACC / 4 + 384 + tid];
        #pragma unroll
        for (int w = 0; w < 16; ++w) s += smf[SM_DP / 4 + w * D_ + tid];
        smf[CX_HL / 4 + tid] = s;
    }
    __syncthreads();

    // ---- cross cosine-attention over hist_2 + relu(h @ W) ----
    if (tid < 32) {
        float s = 0.f;
        #pragma unroll
        for (int c = 0; c < 4; ++c) { float v = smf[CX_HL / 4 + tid + 32 * c]; s += v * v; }
        #pragma unroll
        for (int o = 16; o; o >>= 1) s += __shfl_xor_sync(0xffffffffu, s, o);
        if (tid == 0) smf[CX_IQ / 4] = rsqrtf(s + EPSF);
    }
    __syncthreads();
    {
        const float invq = smf[CX_IQ / 4];
        const float* H2 = h2 + (size_t)b * 256 * D_;
        const float q0 = smf[CX_HL / 4 + lane * 4],     q1 = smf[CX_HL / 4 + lane * 4 + 1];
        const float q2 = smf[CX_HL / 4 + lane * 4 + 2], q3 = smf[CX_HL / 4 + lane * 4 + 3];
        float a0 = 0.f, a1 = 0.f, a2 = 0.f, a3 = 0.f, wp = 0.f;
        for (int k = wid; k < 256; k += 16) {
            float4 v = ((const float4*)(H2 + k * D_))[lane];
            float dot = v.x * q0 + v.y * q1 + v.z * q2 + v.w * q3;
            float nk  = v.x * v.x + v.y * v.y + v.z * v.z + v.w * v.w;
            #pragma unroll
            for (int o = 16; o; o >>= 1) {
                dot += __shfl_xor_sync(0xffffffffu, dot, o);
                nk  += __shfl_xor_sync(0xffffffffu, nk,  o);
            }
            float w = __expf(dot * rsqrtf(nk + EPSF) * invq)
                    * ((seq1[b * 256 + k] != 0) ? 1.f : 0.f);
            wp += w;
            a0 += w * v.x; a1 += w * v.y; a2 += w * v.z; a3 += w * v.w;
        }
        if (lane == 0) smf[CX_WS / 4 + wid] = wp;
        smf[CX_HA / 4 + wid * D_ + lane * 4]     = a0;
        smf[CX_HA / 4 + wid * D_ + lane * 4 + 1] = a1;
        smf[CX_HA / 4 + wid * D_ + lane * 4 + 2] = a2;
        smf[CX_HA / 4 + wid * D_ + lane * 4 + 3] = a3;
    }
    __syncthreads();
    if (tid < D_) {
        float ws = 0.f, s = 0.f;
        #pragma unroll
        for (int w = 0; w < 16; ++w) { ws += smf[CX_WS / 4 + w]; s += smf[CX_HA / 4 + w * D_ + tid]; }
        smf[CX_HV / 4 + tid] = s / ws;
    }
    __syncthreads();
    if (tid < D_) {
        float o = 0.f;
        #pragma unroll 8
        for (int d = 0; d < D_; ++d) o += smf[CX_HV / 4 + d] * W[d * D_ + tid];
        out[b * D_ + tid] = fmaxf(o, 0.f);
    }
}

extern "C" void kernel_launch(void* const* d_in, const int* in_sizes, int n_in,
                              void* d_out, int out_size)
{
    const int*   seq  = (const int*)d_in[0];
    const int*   last = (const int*)d_in[1];
    const int*   seq1 = (const int*)d_in[2];
    const float* h1   = (const float*)d_in[3];
    const float* h2   = (const float*)d_in[4];
    const float* W    = (const float*)d_in[5];
    float* out = (float*)d_out;

    cudaFuncSetAttribute(fused_itd, cudaFuncAttributeMaxDynamicSharedMemorySize, SM_TOT);
    fused_itd<<<B_, 512, SM_TOT>>>(seq, last, seq1, h1, h2, W, out);
}